// round 1
// baseline (speedup 1.0000x reference)
#include <cuda_runtime.h>

#define N_NODES_MAX 50000
#define E_MAX       800000
#define F_IN  128
#define F_HID 128
#define F_OUT 64

// ---------------- scratch (device globals; no allocation allowed) ----------
__device__ float g_deg [N_NODES_MAX];
__device__ float g_dinv[N_NODES_MAX];
__device__ int2  g_edge[E_MAX];
__device__ float g_norm[E_MAX];
__device__ float g_h   [(size_t)N_NODES_MAX * F_IN];   // x @ W1
__device__ float g_out1[(size_t)N_NODES_MAX * F_HID];  // aggregated layer-1 (pre-bias/relu)
__device__ float g_t   [(size_t)N_NODES_MAX * F_OUT];  // relu(h1) @ W2
__device__ int   g_is64;

// ---------------- helpers --------------------------------------------------
__device__ __forceinline__ void red_add_v4(float* addr, float4 v) {
    asm volatile("red.global.add.v4.f32 [%0], {%1,%2,%3,%4};"
                 :: "l"(addr), "f"(v.x), "f"(v.y), "f"(v.z), "f"(v.w)
                 : "memory");
}

__device__ __forceinline__ int load_edge_idx(const void* ei, size_t pos) {
    if (g_is64) return (int)((const long long*)ei)[pos];
    return ((const int*)ei)[pos];
}

// ---------------- dtype detection (int64 vs int32 edge_index) --------------
__global__ void k_detect(const int* __restrict__ ei32) {
    // if int64 little-endian with values in [0, 50000), every odd 32-bit word is 0
    int allzero = 1;
    for (int i = 1; i < 256; i += 2)
        if (ei32[i] != 0) allzero = 0;
    g_is64 = allzero;
}

// ---------------- degree / norm -------------------------------------------
__global__ void k_init_deg(int n) {
    int i = blockIdx.x * blockDim.x + threadIdx.x;
    if (i < n) g_deg[i] = 1.0f;     // self-loop weight 1
}

__global__ void k_accum_deg(const void* __restrict__ ei,
                            const float* __restrict__ ew, int e) {
    int i = blockIdx.x * blockDim.x + threadIdx.x;
    if (i < e) {
        int c = load_edge_idx(ei, (size_t)e + i);
        atomicAdd(&g_deg[c], ew[i]);
    }
}

__global__ void k_dinv(int n) {
    int i = blockIdx.x * blockDim.x + threadIdx.x;
    if (i < n) {
        float d = g_deg[i];
        g_dinv[i] = (d > 0.f) ? rsqrtf(d) : 0.f;
    }
}

__global__ void k_edge_prep(const void* __restrict__ ei,
                            const float* __restrict__ ew, int e) {
    int i = blockIdx.x * blockDim.x + threadIdx.x;
    if (i < e) {
        int r = load_edge_idx(ei, (size_t)i);
        int c = load_edge_idx(ei, (size_t)e + i);
        g_edge[i] = make_int2(r, c);
        g_norm[i] = g_dinv[r] * ew[i] * g_dinv[c];
    }
}

// ---------------- GEMM1: h = x @ W1 ; out1 = h * dinv^2 (self loop) --------
// tile 64 rows x 128 cols, 256 threads, 4x8 per thread
__global__ __launch_bounds__(256) void k_gemm1(const float* __restrict__ x,
                                               const float* __restrict__ W1,
                                               int M) {
    __shared__ float Xs[64][36];     // [row][k], padded
    __shared__ float Ws[32][128];    // [k][n]
    const int t = threadIdx.x;
    const int tidx = t & 15;         // col group: cols tidx*8 .. +7
    const int tidy = t >> 4;         // row group: rows tidy*4 .. +3
    const int rowbase = blockIdx.x * 64;

    float acc[4][8];
#pragma unroll
    for (int r = 0; r < 4; r++)
#pragma unroll
        for (int c = 0; c < 8; c++) acc[r][c] = 0.f;

    for (int kb = 0; kb < 128; kb += 32) {
#pragma unroll
        for (int i = 0; i < 2; i++) {              // 64x32 floats = 512 f4
            int idx = t + i * 256;
            int r = idx >> 3, kq = idx & 7;
            int grow = rowbase + r;
            float4 v = make_float4(0.f, 0.f, 0.f, 0.f);
            if (grow < M)
                v = *(const float4*)(x + (size_t)grow * 128 + kb + kq * 4);
            *(float4*)&Xs[r][kq * 4] = v;
        }
#pragma unroll
        for (int i = 0; i < 4; i++) {              // 32x128 floats = 1024 f4
            int idx = t + i * 256;
            int k = idx >> 5, nq = idx & 31;
            *(float4*)&Ws[k][nq * 4] =
                *(const float4*)(W1 + (size_t)(kb + k) * 128 + nq * 4);
        }
        __syncthreads();
#pragma unroll
        for (int k = 0; k < 32; k++) {
            float aa[4];
#pragma unroll
            for (int r = 0; r < 4; r++) aa[r] = Xs[tidy * 4 + r][k];
            float4 b0 = *(const float4*)&Ws[k][tidx * 8];
            float4 b1 = *(const float4*)&Ws[k][tidx * 8 + 4];
            float bb[8] = {b0.x, b0.y, b0.z, b0.w, b1.x, b1.y, b1.z, b1.w};
#pragma unroll
            for (int r = 0; r < 4; r++)
#pragma unroll
                for (int c = 0; c < 8; c++)
                    acc[r][c] = fmaf(aa[r], bb[c], acc[r][c]);
        }
        __syncthreads();
    }

#pragma unroll
    for (int r = 0; r < 4; r++) {
        int grow = rowbase + tidy * 4 + r;
        if (grow < M) {
            float s = g_dinv[grow]; s = s * s;
            float* hp = g_h    + (size_t)grow * 128 + tidx * 8;
            float* op = g_out1 + (size_t)grow * 128 + tidx * 8;
            float4 v0 = make_float4(acc[r][0], acc[r][1], acc[r][2], acc[r][3]);
            float4 v1 = make_float4(acc[r][4], acc[r][5], acc[r][6], acc[r][7]);
            *(float4*)hp       = v0;
            *((float4*)hp + 1) = v1;
            float4 w0 = make_float4(v0.x * s, v0.y * s, v0.z * s, v0.w * s);
            float4 w1 = make_float4(v1.x * s, v1.y * s, v1.z * s, v1.w * s);
            *(float4*)op       = w0;
            *((float4*)op + 1) = w1;
        }
    }
}

// ---------------- scatter layer 1: one warp per edge (128 floats) ----------
__global__ __launch_bounds__(256) void k_scatter1(int e) {
    int warp = (blockIdx.x * blockDim.x + threadIdx.x) >> 5;
    int lane = threadIdx.x & 31;
    if (warp >= e) return;
    int2 rc = g_edge[warp];
    float nm = g_norm[warp];
    float4 v = *(const float4*)(g_h + (size_t)rc.x * 128 + lane * 4);
    v.x *= nm; v.y *= nm; v.z *= nm; v.w *= nm;
    red_add_v4(g_out1 + (size_t)rc.y * 128 + lane * 4, v);
}

// ---------------- GEMM2: t = relu(out1+b1) @ W2 ; d_out = b2 + t*dinv^2 ----
// tile 64 rows x 64 cols, 256 threads, 4x4 per thread
__global__ __launch_bounds__(256) void k_gemm2(const float* __restrict__ W2,
                                               const float* __restrict__ b1,
                                               const float* __restrict__ b2,
                                               float* __restrict__ out, int M) {
    __shared__ float Xs[64][36];
    __shared__ float Ws[32][64];
    __shared__ float Bs1[128];
    __shared__ float Bs2[64];
    const int t = threadIdx.x;
    const int tidx = t & 15;         // cols tidx*4 .. +3
    const int tidy = t >> 4;         // rows tidy*4 .. +3
    const int rowbase = blockIdx.x * 64;

    if (t < 128) Bs1[t] = b1[t];
    if (t < 64)  Bs2[t] = b2[t];
    __syncthreads();

    float acc[4][4];
#pragma unroll
    for (int r = 0; r < 4; r++)
#pragma unroll
        for (int c = 0; c < 4; c++) acc[r][c] = 0.f;

    for (int kb = 0; kb < 128; kb += 32) {
#pragma unroll
        for (int i = 0; i < 2; i++) {              // A tile with bias+relu
            int idx = t + i * 256;
            int r = idx >> 3, kq = idx & 7;
            int grow = rowbase + r;
            float4 v = make_float4(0.f, 0.f, 0.f, 0.f);
            if (grow < M) {
                v = *(const float4*)(g_out1 + (size_t)grow * 128 + kb + kq * 4);
                v.x = fmaxf(v.x + Bs1[kb + kq * 4 + 0], 0.f);
                v.y = fmaxf(v.y + Bs1[kb + kq * 4 + 1], 0.f);
                v.z = fmaxf(v.z + Bs1[kb + kq * 4 + 2], 0.f);
                v.w = fmaxf(v.w + Bs1[kb + kq * 4 + 3], 0.f);
            }
            *(float4*)&Xs[r][kq * 4] = v;
        }
#pragma unroll
        for (int i = 0; i < 2; i++) {              // 32x64 floats = 512 f4
            int idx = t + i * 256;
            int k = idx >> 4, nq = idx & 15;
            *(float4*)&Ws[k][nq * 4] =
                *(const float4*)(W2 + (size_t)(kb + k) * 64 + nq * 4);
        }
        __syncthreads();
#pragma unroll
        for (int k = 0; k < 32; k++) {
            float aa[4];
#pragma unroll
            for (int r = 0; r < 4; r++) aa[r] = Xs[tidy * 4 + r][k];
            float4 b = *(const float4*)&Ws[k][tidx * 4];
            float bb[4] = {b.x, b.y, b.z, b.w};
#pragma unroll
            for (int r = 0; r < 4; r++)
#pragma unroll
                for (int c = 0; c < 4; c++)
                    acc[r][c] = fmaf(aa[r], bb[c], acc[r][c]);
        }
        __syncthreads();
    }

#pragma unroll
    for (int r = 0; r < 4; r++) {
        int grow = rowbase + tidy * 4 + r;
        if (grow < M) {
            float s = g_dinv[grow]; s = s * s;
            float4 tv = make_float4(acc[r][0], acc[r][1], acc[r][2], acc[r][3]);
            *(float4*)(g_t + (size_t)grow * 64 + tidx * 4) = tv;
            float4 ov;
            ov.x = Bs2[tidx * 4 + 0] + tv.x * s;
            ov.y = Bs2[tidx * 4 + 1] + tv.y * s;
            ov.z = Bs2[tidx * 4 + 2] + tv.z * s;
            ov.w = Bs2[tidx * 4 + 3] + tv.w * s;
            *(float4*)(out + (size_t)grow * 64 + tidx * 4) = ov;
        }
    }
}

// ---------------- scatter layer 2: half-warp per edge (64 floats) ----------
__global__ __launch_bounds__(256) void k_scatter2(float* __restrict__ out, int e) {
    int gid = blockIdx.x * blockDim.x + threadIdx.x;
    int edge = gid >> 4;
    int lane = gid & 15;
    if (edge >= e) return;
    int2 rc = g_edge[edge];
    float nm = g_norm[edge];
    float4 v = *(const float4*)(g_t + (size_t)rc.x * 64 + lane * 4);
    v.x *= nm; v.y *= nm; v.z *= nm; v.w *= nm;
    red_add_v4(out + (size_t)rc.y * 64 + lane * 4, v);
}

// ---------------- entry ----------------------------------------------------
extern "C" void kernel_launch(void* const* d_in, const int* in_sizes, int n_in,
                              void* d_out, int out_size) {
    const float* x  = (const float*)d_in[0];
    const void*  ei = d_in[1];                  // int64 or int32 (detected on device)
    const float* ew = (const float*)d_in[2];
    const float* W1 = (const float*)d_in[3];
    const float* b1 = (const float*)d_in[4];
    const float* W2 = (const float*)d_in[5];
    const float* b2 = (const float*)d_in[6];
    float* out = (float*)d_out;

    int N = in_sizes[0] / F_IN;     // 50000
    int E = in_sizes[2];            // 800000

    k_detect<<<1, 1>>>((const int*)ei);
    k_init_deg<<<(N + 255) / 256, 256>>>(N);
    k_accum_deg<<<(E + 255) / 256, 256>>>(ei, ew, E);
    k_dinv<<<(N + 255) / 256, 256>>>(N);
    k_edge_prep<<<(E + 255) / 256, 256>>>(ei, ew, E);

    k_gemm1<<<(N + 63) / 64, 256>>>(x, W1, N);
    k_scatter1<<<(E + 7) / 8, 256>>>(E);
    k_gemm2<<<(N + 63) / 64, 256>>>(W2, b1, b2, out, N);
    k_scatter2<<<(E + 15) / 16, 256>>>(out, E);
}